// round 9
// baseline (speedup 1.0000x reference)
#include <cuda_runtime.h>

// ---------------- scratch (sizes fixed: N=50000, E=400000) ----------------
#define NEDGE 400000
__device__ float g_agg [50048  * 80];   // per-node gated sums: 32 silu'd scalars + 48 vec comps
__device__ float g_agg2[50048  * 40];   // after Lms/Lmv fold: 16 s + 24 v
__device__ float g_mid [NEDGE * 40];    // stage-1 per-edge intermediate (e-major)
__device__ float g_gate[16 * NEDGE];    // sigmoid gates, t-major [16][E]
__device__ float g_F   [192 * NEDGE];   // stage2 scalar-path features, k-major [192][E]
__device__ float g_hid [48 * 50048];    // update hidden scalars (silu'd / sigm'd), t-major
__device__ float g_hidv[48 * 50048];    // update gated vector comps, (k*3+c)-major

#define I2f   0.70710678118654752f
#define I3f   0.57735026918962576f
#define R128f 0.08838834764831845f
#define R32f  0.17677669529663687f

__device__ __forceinline__ float sigm_f(float x) {
    return __fdividef(1.f, 1.f + __expf(-x));
}

__device__ __forceinline__ void wload(float* __restrict__ dst, const float* __restrict__ src,
                                      int nf4, float sc, int tid, int nt) {
    for (int t = tid; t < nf4; t += nt) {
        float4 v = reinterpret_cast<const float4*>(src)[t];
        v.x *= sc; v.y *= sc; v.z *= sc; v.w *= sc;
        reinterpret_cast<float4*>(dst)[t] = v;
    }
}
__device__ __forceinline__ void wslice(float* __restrict__ dst, const float* __restrict__ src,
                                       int rows, int srcF4, int dstF4, int off4,
                                       float sc, int tid) {
    int n = rows * dstF4;
    for (int t = tid; t < n; t += 128) {
        int r = t / dstF4, o = t - r * dstF4;
        float4 v = reinterpret_cast<const float4*>(src)[r * srcF4 + off4 + o];
        v.x *= sc; v.y *= sc; v.z *= sc; v.w *= sc;
        reinterpret_cast<float4*>(dst)[t] = v;
    }
}
template<int K4>
__device__ __forceinline__ void fma_k(float* acc, const float* __restrict__ w, float p) {
#pragma unroll
    for (int k = 0; k < K4; k++) {
        float4 ww = reinterpret_cast<const float4*>(w)[k];
        acc[4 * k + 0] += p * ww.x; acc[4 * k + 1] += p * ww.y;
        acc[4 * k + 2] += p * ww.z; acc[4 * k + 3] += p * ww.w;
    }
}
__device__ __forceinline__ void fma_vo8(float* vo, const float* A, float bx, float by, float bz) {
#pragma unroll
    for (int k = 0; k < 8; k++) {
        vo[3 * k + 0] += A[k] * bx; vo[3 * k + 1] += A[k] * by; vo[3 * k + 2] += A[k] * bz;
    }
}
__device__ __forceinline__ void fma_cross8(float* vo, const float* __restrict__ w,
                                           float cx, float cy, float cz) {
#pragma unroll
    for (int q = 0; q < 2; q++) {
        float4 ww = reinterpret_cast<const float4*>(w)[q];
        vo[12 * q + 0]  += cx * ww.x; vo[12 * q + 1]  += cy * ww.x; vo[12 * q + 2]  += cz * ww.x;
        vo[12 * q + 3]  += cx * ww.y; vo[12 * q + 4]  += cy * ww.y; vo[12 * q + 5]  += cz * ww.y;
        vo[12 * q + 6]  += cx * ww.z; vo[12 * q + 7]  += cy * ww.z; vo[12 * q + 8]  += cz * ww.z;
        vo[12 * q + 9]  += cx * ww.w; vo[12 * q + 10] += cy * ww.w; vo[12 * q + 11] += cz * ww.w;
    }
}
__device__ __forceinline__ void ld_f(float* dst, const float* __restrict__ src, int nf4) {
#pragma unroll
    for (int q = 0; q < 6; q++)
        if (q < nf4) reinterpret_cast<float4*>(dst)[q] =
            __ldg(reinterpret_cast<const float4*>(src) + q);
}

// ---------------- kernels ----------------
__global__ void zero_kernel(int n) {
    int i = blockIdx.x * 256 + threadIdx.x;
    if (i < n) g_agg[i] = 0.f;
}

// stage1 scalar paths: ms[16] -> g_mid[e][0:16)
__global__ __launch_bounds__(128, 6) void stage1_s_kernel(
    const float* __restrict__ ns, const float* __restrict__ nv,
    const int* __restrict__ eidx,
    const float* __restrict__ W1ss, const float* __restrict__ W1vvs, int E)
{
    __shared__ float wss[4096], wd[1024];
    int tid = threadIdx.x;
    wload(wss, W1ss, 1024, I2f / 16.f, tid, 128);
    wload(wd, W1vvs, 256, I2f * I3f / 8.f, tid, 128);
    __syncthreads();
    int e = blockIdx.x * 128 + tid;
    if (e >= E) return;
    int r = eidx[e], c = eidx[E + e];

    float acc[16];
#pragma unroll
    for (int k = 0; k < 16; k++) acc[k] = 0.f;
    {
        float s1[16], s2[16];
        ld_f(s1, ns + (size_t)r * 16, 4);
        ld_f(s2, ns + (size_t)c * 16, 4);
#pragma unroll 1
        for (int i = 0; i < 16; i++) {
            float a = s1[i];
#pragma unroll 2
            for (int j = 0; j < 16; j++)
                fma_k<4>(acc, &wss[(i * 16 + j) * 16], a * s2[j]);
        }
    }
    {
        float v1[24], v2[24];
        ld_f(v1, nv + (size_t)r * 24, 6);
        ld_f(v2, nv + (size_t)c * 24, 6);
#pragma unroll 1
        for (int i = 0; i < 8; i++) {
            float ax = v1[3 * i], ay = v1[3 * i + 1], az = v1[3 * i + 2];
#pragma unroll 2
            for (int j = 0; j < 8; j++) {
                float d = ax * v2[3 * j] + ay * v2[3 * j + 1] + az * v2[3 * j + 2];
                fma_k<4>(acc, &wd[(i * 8 + j) * 16], d);
            }
        }
    }
    float* o = &g_mid[(size_t)e * 40];
#pragma unroll
    for (int q = 0; q < 4; q++)
        reinterpret_cast<float4*>(o)[q] = reinterpret_cast<float4*>(acc)[q];
}

// stage1 vector paths: mv[8][3] -> g_mid[e][16:40)
__global__ __launch_bounds__(128, 6) void stage1_v_kernel(
    const float* __restrict__ ns, const float* __restrict__ nv,
    const int* __restrict__ eidx,
    const float* __restrict__ W1sv, const float* __restrict__ W1vs,
    const float* __restrict__ W1vvv, int E)
{
    __shared__ float wsv[1024], wvs[1024], wvvv[512];
    int tid = threadIdx.x;
    wload(wsv, W1sv, 256, I3f * R128f, tid, 128);
    wload(wvs, W1vs, 256, I3f * R128f, tid, 128);
    wload(wvvv, W1vvv, 128, I2f * I3f / 8.f, tid, 128);
    __syncthreads();
    int e = blockIdx.x * 128 + tid;
    if (e >= E) return;
    int r = eidx[e], c = eidx[E + e];

    float vo[24];
#pragma unroll
    for (int k = 0; k < 24; k++) vo[k] = 0.f;
    float v2[24];
    ld_f(v2, nv + (size_t)c * 24, 6);
    {   // 0x1 -> 1
        float s1[16];
        ld_f(s1, ns + (size_t)r * 16, 4);
#pragma unroll 1
        for (int j = 0; j < 8; j++) {
            float A[8];
#pragma unroll
            for (int k = 0; k < 8; k++) A[k] = 0.f;
#pragma unroll 2
            for (int i = 0; i < 16; i++)
                fma_k<2>(A, &wsv[(i * 8 + j) * 8], s1[i]);
            fma_vo8(vo, A, v2[3 * j], v2[3 * j + 1], v2[3 * j + 2]);
        }
    }
    float v1[24];
    ld_f(v1, nv + (size_t)r * 24, 6);
    {   // 1x0 -> 1
        float s2[16];
        ld_f(s2, ns + (size_t)c * 16, 4);
#pragma unroll 1
        for (int i = 0; i < 8; i++) {
            float A[8];
#pragma unroll
            for (int k = 0; k < 8; k++) A[k] = 0.f;
#pragma unroll 2
            for (int j = 0; j < 16; j++)
                fma_k<2>(A, &wvs[(i * 16 + j) * 8], s2[j]);
            fma_vo8(vo, A, v1[3 * i], v1[3 * i + 1], v1[3 * i + 2]);
        }
    }
    // 1x1 -> 1
#pragma unroll 1
    for (int i = 0; i < 8; i++) {
        float ax = v1[3 * i], ay = v1[3 * i + 1], az = v1[3 * i + 2];
#pragma unroll 1
        for (int j = 0; j < 8; j++) {
            float bx = v2[3 * j], by = v2[3 * j + 1], bz = v2[3 * j + 2];
            fma_cross8(vo, &wvvv[(i * 8 + j) * 8],
                       ay * bz - az * by, az * bx - ax * bz, ax * by - ay * bx);
        }
    }
    float* o = &g_mid[(size_t)e * 40 + 16];
#pragma unroll
    for (int q = 0; q < 6; q++)
        reinterpret_cast<float4*>(o)[q] = reinterpret_cast<float4*>(vo)[q];
}

// ---- stage2 scalar path, GEMM formulation ----
// prep: F[e] = { ms_i*es_j (128), dot(mv_i, ev_j) (64) }, stored k-major g_F[f][e]
__global__ __launch_bounds__(128) void stage2_prep_kernel(
    const float* __restrict__ edge_s, const float* __restrict__ edge_v, int E)
{
    int e = blockIdx.x * 128 + threadIdx.x;
    if (e >= E) return;
    float ms[16], mv[24], es[8], ev[24];
    {
        const float* m = &g_mid[(size_t)e * 40];
#pragma unroll
        for (int q = 0; q < 4; q++) reinterpret_cast<float4*>(ms)[q] = reinterpret_cast<const float4*>(m)[q];
#pragma unroll
        for (int q = 0; q < 6; q++) reinterpret_cast<float4*>(mv)[q] = reinterpret_cast<const float4*>(m)[4 + q];
    }
    ld_f(es, edge_s + (size_t)e * 8, 2);
    ld_f(ev, edge_v + (size_t)e * 24, 6);
#pragma unroll 1
    for (int i = 0; i < 16; i++) {
        float a = ms[i];
#pragma unroll
        for (int j = 0; j < 8; j++)
            g_F[(size_t)(i * 8 + j) * NEDGE + e] = a * es[j];
    }
#pragma unroll 1
    for (int i = 0; i < 8; i++) {
        float ax = mv[3 * i], ay = mv[3 * i + 1], az = mv[3 * i + 2];
#pragma unroll
        for (int j = 0; j < 8; j++)
            g_F[(size_t)(128 + i * 8 + j) * NEDGE + e] =
                ax * ev[3 * j] + ay * ev[3 * j + 1] + az * ev[3 * j + 2];
    }
}

// gemm: C[64-edge tile][48] = F_tile[192] x W[192][48]; epilogue silu->atomic / sigm->gate
#define GT 96
__global__ __launch_bounds__(GT) void stage2_gemm_kernel(
    const int* __restrict__ eidx,
    const float* __restrict__ W2ss, const float* __restrict__ W2vvs, int E)
{
    __shared__ float Fs[16][64];
    __shared__ float Ws[16][48];
    int tid = threadIdx.x;
    int e0 = blockIdx.x * 64;
    int egrp = tid & 7;        // edge group: edges e0 + egrp*8 .. +7
    int kgrp = tid >> 3;       // k group: k = kgrp*4 .. +3
    float acc[8][4];
#pragma unroll
    for (int a = 0; a < 8; a++)
#pragma unroll
        for (int b = 0; b < 4; b++) acc[a][b] = 0.f;

    bool full = (e0 + 64 <= E);
#pragma unroll 1
    for (int ch = 0; ch < 12; ch++) {
        __syncthreads();
        // W chunk: rows f = ch*16 + r of combined [192][48]
        for (int t = tid; t < 16 * 48; t += GT) {
            int r = t / 48, k = t - r * 48;
            int f = ch * 16 + r;
            float w = (f < 128) ? W2ss[f * 48 + k] * (I2f * R128f)
                                : W2vvs[(f - 128) * 48 + k] * (I2f * I3f / 8.f);
            Ws[r][k] = w;
        }
        // F chunk: 16 rows x 64 edges, coalesced
        for (int t = tid; t < 16 * 16; t += GT) {
            int r = t >> 4, q = t & 15;
            const float* base = g_F + (size_t)(ch * 16 + r) * NEDGE + e0;
            if (full) {
                reinterpret_cast<float4*>(&Fs[r][0])[q] =
                    __ldg(reinterpret_cast<const float4*>(base) + q);
            } else {
#pragma unroll
                for (int cc = 0; cc < 4; cc++) {
                    int e = e0 + q * 4 + cc;
                    Fs[r][q * 4 + cc] = (e < E) ? base[q * 4 + cc] : 0.f;
                }
            }
        }
        __syncthreads();
#pragma unroll
        for (int f = 0; f < 16; f++) {
            float4 fa = *reinterpret_cast<const float4*>(&Fs[f][egrp * 8]);
            float4 fb = *reinterpret_cast<const float4*>(&Fs[f][egrp * 8 + 4]);
            float4 w  = *reinterpret_cast<const float4*>(&Ws[f][kgrp * 4]);
            float fe[8] = {fa.x, fa.y, fa.z, fa.w, fb.x, fb.y, fb.z, fb.w};
            float wk[4] = {w.x, w.y, w.z, w.w};
#pragma unroll
            for (int a = 0; a < 8; a++)
#pragma unroll
                for (int b = 0; b < 4; b++)
                    acc[a][b] += fe[a] * wk[b];
        }
    }
    // epilogue
    int kbase = kgrp * 4;
#pragma unroll 1
    for (int a = 0; a < 8; a++) {
        int e = e0 + egrp * 8 + a;
        if (e >= E) continue;
        if (kbase < 32) {
            int c = __ldg(eidx + E + e);
            float* dst = &g_agg[(size_t)c * 80 + kbase];
#pragma unroll
            for (int b = 0; b < 4; b++) {
                float v = acc[a][b];
                atomicAdd(dst + b, v * sigm_f(v));
            }
        } else {
#pragma unroll
            for (int b = 0; b < 4; b++) {
                float v = acc[a][b];
                g_gate[(size_t)(kbase - 32 + b) * E + e] = sigm_f(v);
            }
        }
    }
}

// stage2 vector paths, 2 k-chunks of 8. gate from g_gate, atomic into agg vec slots.
__global__ __launch_bounds__(128, 5) void stage2_v_kernel(
    const float* __restrict__ edge_s, const float* __restrict__ edge_v,
    const int* __restrict__ eidx,
    const float* __restrict__ W2sv, const float* __restrict__ W2vs,
    const float* __restrict__ W2vvv, int E)
{
    __shared__ float wsv[1024], wvs[1024], wvvv[512];
    int tid = threadIdx.x;
    int e = blockIdx.x * 128 + tid;
    bool act = e < E;
    int c = 0;
    float ms[16], mv[24], es[8], ev[24];
    if (act) {
        c = eidx[E + e];
        const float* m = &g_mid[(size_t)e * 40];
#pragma unroll
        for (int q = 0; q < 4; q++) reinterpret_cast<float4*>(ms)[q] = reinterpret_cast<const float4*>(m)[q];
#pragma unroll
        for (int q = 0; q < 6; q++) reinterpret_cast<float4*>(mv)[q] = reinterpret_cast<const float4*>(m)[4 + q];
        ld_f(es, edge_s + (size_t)e * 8, 2);
        ld_f(ev, edge_v + (size_t)e * 24, 6);
    }
#pragma unroll 1
    for (int ch = 0; ch < 2; ch++) {
        __syncthreads();
        wslice(wsv, W2sv, 128, 4, 2, ch * 2, I3f * R128f, tid);
        wslice(wvs, W2vs, 64, 4, 2, ch * 2, I3f / 8.f, tid);
        wslice(wvvv, W2vvv, 64, 4, 2, ch * 2, I2f * I3f / 8.f, tid);
        __syncthreads();
        if (!act) continue;
        float vo[24];
#pragma unroll
        for (int k = 0; k < 24; k++) vo[k] = 0.f;
#pragma unroll 1
        for (int j = 0; j < 8; j++) {
            float A[8];
#pragma unroll
            for (int k = 0; k < 8; k++) A[k] = 0.f;
#pragma unroll 2
            for (int i = 0; i < 16; i++)
                fma_k<2>(A, &wsv[(i * 8 + j) * 8], ms[i]);
            fma_vo8(vo, A, ev[3 * j], ev[3 * j + 1], ev[3 * j + 2]);
        }
#pragma unroll 1
        for (int i = 0; i < 8; i++) {
            float A[8];
#pragma unroll
            for (int k = 0; k < 8; k++) A[k] = 0.f;
#pragma unroll 2
            for (int j = 0; j < 8; j++)
                fma_k<2>(A, &wvs[(i * 8 + j) * 8], es[j]);
            fma_vo8(vo, A, mv[3 * i], mv[3 * i + 1], mv[3 * i + 2]);
        }
#pragma unroll 1
        for (int i = 0; i < 8; i++) {
            float ax = mv[3 * i], ay = mv[3 * i + 1], az = mv[3 * i + 2];
#pragma unroll 1
            for (int j = 0; j < 8; j++) {
                float bx = ev[3 * j], by = ev[3 * j + 1], bz = ev[3 * j + 2];
                fma_cross8(vo, &wvvv[(i * 8 + j) * 8],
                           ay * bz - az * by, az * bx - ax * bz, ax * by - ay * bx);
            }
        }
#pragma unroll
        for (int t = 0; t < 8; t++) {
            float g = g_gate[(size_t)(ch * 8 + t) * E + e];
            float* dst = &g_agg[(size_t)c * 80 + 32 + (ch * 8 + t) * 3];
            atomicAdd(dst + 0, vo[3 * t + 0] * g);
            atomicAdd(dst + 1, vo[3 * t + 1] * g);
            atomicAdd(dst + 2, vo[3 * t + 2] * g);
        }
    }
}

// fold Lms/Lmv into aggregated (post-gate) sums: g_agg[N,80] -> g_agg2[N,40]
__global__ void fold_kernel(const float* __restrict__ Lms, const float* __restrict__ Lmv, int N)
{
    __shared__ float lms[512], lmv[128];
    int tid = threadIdx.x;
    wload(lms, Lms, 128, R32f, tid, 256);
    wload(lmv, Lmv, 32, 0.25f, tid, 256);
    __syncthreads();
    int n = blockIdx.x * 256 + tid;
    if (n >= N) return;
    const float* a = &g_agg[(size_t)n * 80];
    float* o = &g_agg2[(size_t)n * 40];
    float os[16];
#pragma unroll
    for (int k = 0; k < 16; k++) os[k] = 0.f;
#pragma unroll 1
    for (int i = 0; i < 32; i++)
        fma_k<4>(os, &lms[i * 16], a[i]);
#pragma unroll
    for (int k = 0; k < 16; k++) o[k] = os[k];
    float ov[24];
#pragma unroll
    for (int k = 0; k < 24; k++) ov[k] = 0.f;
#pragma unroll 1
    for (int i = 0; i < 16; i++) {
        float ax = a[32 + 3 * i], ay = a[32 + 3 * i + 1], az = a[32 + 3 * i + 2];
        const float* w = &lmv[i * 8];
#pragma unroll
        for (int k = 0; k < 8; k++) {
            float ww = w[k];
            ov[3 * k + 0] += ax * ww; ov[3 * k + 1] += ay * ww; ov[3 * k + 2] += az * ww;
        }
    }
#pragma unroll
    for (int t = 0; t < 24; t++) o[16 + t] = ov[t];
}

// update scalar paths -> g_hid (silu'd for k<32, sigm'd for k>=32)
__global__ __launch_bounds__(128, 5) void update_s_kernel(
    const float* __restrict__ ns, const float* __restrict__ nv,
    const float* __restrict__ W3ss, const float* __restrict__ W3vvs, int N)
{
    __shared__ float ws[4096], wd[1024];
    int tid = threadIdx.x;
    int n = blockIdx.x * 128 + tid;
    bool act = n < N;
    float s1[16], v1[24], s2[16], v2[24];
    if (act) {
        ld_f(s1, ns + (size_t)n * 16, 4);
        ld_f(v1, nv + (size_t)n * 24, 6);
        const float* a = &g_agg2[(size_t)n * 40];
#pragma unroll
        for (int q = 0; q < 4; q++) reinterpret_cast<float4*>(s2)[q] = reinterpret_cast<const float4*>(a)[q];
#pragma unroll
        for (int q = 0; q < 6; q++) reinterpret_cast<float4*>(v2)[q] = reinterpret_cast<const float4*>(a)[4 + q];
    }
#pragma unroll 1
    for (int ch = 0; ch < 3; ch++) {
        __syncthreads();
        wslice(ws, W3ss, 256, 12, 4, ch * 4, I2f / 16.f, tid);
        wslice(wd, W3vvs, 64, 12, 4, ch * 4, I2f * I3f / 8.f, tid);
        __syncthreads();
        if (!act) continue;
        float acc[16];
#pragma unroll
        for (int k = 0; k < 16; k++) acc[k] = 0.f;
#pragma unroll 1
        for (int i = 0; i < 16; i++) {
            float a = s1[i];
#pragma unroll 2
            for (int j = 0; j < 16; j++)
                fma_k<4>(acc, &ws[(i * 16 + j) * 16], a * s2[j]);
        }
#pragma unroll 1
        for (int i = 0; i < 8; i++) {
            float ax = v1[3 * i], ay = v1[3 * i + 1], az = v1[3 * i + 2];
#pragma unroll 2
            for (int j = 0; j < 8; j++) {
                float d = ax * v2[3 * j] + ay * v2[3 * j + 1] + az * v2[3 * j + 2];
                fma_k<4>(acc, &wd[(i * 8 + j) * 16], d);
            }
        }
#pragma unroll
        for (int t = 0; t < 16; t++) {
            float v = (ch < 2) ? acc[t] * sigm_f(acc[t]) : sigm_f(acc[t]);
            g_hid[(size_t)(ch * 16 + t) * N + n] = v;
        }
    }
}

// update vector paths -> gated comps in g_hidv
__global__ __launch_bounds__(128, 5) void update_v_kernel(
    const float* __restrict__ ns, const float* __restrict__ nv,
    const float* __restrict__ W3sv, const float* __restrict__ W3vs,
    const float* __restrict__ W3vvv, int N)
{
    __shared__ float wsv[1024], wvs[1024], wvvv[512];
    int tid = threadIdx.x;
    int n = blockIdx.x * 128 + tid;
    bool act = n < N;
    float s1[16], v1[24], s2[16], v2[24];
    if (act) {
        ld_f(s1, ns + (size_t)n * 16, 4);
        ld_f(v1, nv + (size_t)n * 24, 6);
        const float* a = &g_agg2[(size_t)n * 40];
#pragma unroll
        for (int q = 0; q < 4; q++) reinterpret_cast<float4*>(s2)[q] = reinterpret_cast<const float4*>(a)[q];
#pragma unroll
        for (int q = 0; q < 6; q++) reinterpret_cast<float4*>(v2)[q] = reinterpret_cast<const float4*>(a)[4 + q];
    }
#pragma unroll 1
    for (int ch = 0; ch < 2; ch++) {
        __syncthreads();
        wslice(wsv, W3sv, 128, 4, 2, ch * 2, I3f * R128f, tid);
        wslice(wvs, W3vs, 128, 4, 2, ch * 2, I3f * R128f, tid);
        wslice(wvvv, W3vvv, 64, 4, 2, ch * 2, I2f * I3f / 8.f, tid);
        __syncthreads();
        if (!act) continue;
        float vo[24];
#pragma unroll
        for (int k = 0; k < 24; k++) vo[k] = 0.f;
#pragma unroll 1
        for (int j = 0; j < 8; j++) {
            float A[8];
#pragma unroll
            for (int k = 0; k < 8; k++) A[k] = 0.f;
#pragma unroll 2
            for (int i = 0; i < 16; i++)
                fma_k<2>(A, &wsv[(i * 8 + j) * 8], s1[i]);
            fma_vo8(vo, A, v2[3 * j], v2[3 * j + 1], v2[3 * j + 2]);
        }
#pragma unroll 1
        for (int i = 0; i < 8; i++) {
            float A[8];
#pragma unroll
            for (int k = 0; k < 8; k++) A[k] = 0.f;
#pragma unroll 2
            for (int j = 0; j < 16; j++)
                fma_k<2>(A, &wvs[(i * 16 + j) * 8], s2[j]);
            fma_vo8(vo, A, v1[3 * i], v1[3 * i + 1], v1[3 * i + 2]);
        }
#pragma unroll 1
        for (int i = 0; i < 8; i++) {
            float ax = v1[3 * i], ay = v1[3 * i + 1], az = v1[3 * i + 2];
#pragma unroll 1
            for (int j = 0; j < 8; j++) {
                float bx = v2[3 * j], by = v2[3 * j + 1], bz = v2[3 * j + 2];
                float cx = ay * bz - az * by, cy = az * bx - ax * bz, cz = ax * by - ay * bx;
                fma_cross8(vo, &wvvv[(i * 8 + j) * 8], cx, cy, cz);
            }
        }
#pragma unroll
        for (int t = 0; t < 8; t++) {
            float g = g_hid[(size_t)(32 + ch * 8 + t) * N + n];
#pragma unroll
            for (int cc = 0; cc < 3; cc++)
                g_hidv[(size_t)((ch * 8 + t) * 3 + cc) * N + n] = vo[3 * t + cc] * g;
        }
    }
}

// final: apply Lus/Luv per node, write out[N,40]
__global__ void final_kernel(const float* __restrict__ Lus, const float* __restrict__ Luv,
                             float* __restrict__ out, int N)
{
    __shared__ float lus[512], luv[128];
    int tid = threadIdx.x;
    wload(lus, Lus, 128, R32f, tid, 256);
    wload(luv, Luv, 32, 0.25f, tid, 256);
    __syncthreads();
    int n = blockIdx.x * 256 + tid;
    if (n >= N) return;
    float os[16];
#pragma unroll
    for (int k = 0; k < 16; k++) os[k] = 0.f;
#pragma unroll 1
    for (int i = 0; i < 32; i++)
        fma_k<4>(os, &lus[i * 16], g_hid[(size_t)i * N + n]);
    float ov[24];
#pragma unroll
    for (int k = 0; k < 24; k++) ov[k] = 0.f;
#pragma unroll 1
    for (int i = 0; i < 16; i++) {
        float ax = g_hidv[(size_t)(3 * i + 0) * N + n];
        float ay = g_hidv[(size_t)(3 * i + 1) * N + n];
        float az = g_hidv[(size_t)(3 * i + 2) * N + n];
        const float* w = &luv[i * 8];
#pragma unroll
        for (int k = 0; k < 8; k++) {
            float ww = w[k];
            ov[3 * k + 0] += ax * ww; ov[3 * k + 1] += ay * ww; ov[3 * k + 2] += az * ww;
        }
    }
    float* o = out + (size_t)n * 40;
#pragma unroll
    for (int k = 0; k < 16; k++) o[k] = os[k];
#pragma unroll
    for (int t = 0; t < 24; t++) o[16 + t] = ov[t];
}

// ---------------- launch ----------------
extern "C" void kernel_launch(void* const* d_in, const int* in_sizes, int n_in,
                              void* d_out, int out_size) {
    const float* node_s = (const float*)d_in[0];
    const float* node_v = (const float*)d_in[1];
    const float* edge_s = (const float*)d_in[3];
    const float* edge_v = (const float*)d_in[4];
    const int*   eidx   = (const int*)d_in[5];
    const float* W1ss = (const float*)d_in[6];
    const float* W1sv = (const float*)d_in[7];
    const float* W1vs = (const float*)d_in[8];
    const float* W1vvs = (const float*)d_in[9];
    const float* W1vvv = (const float*)d_in[10];
    const float* W2ss = (const float*)d_in[11];
    const float* W2sv = (const float*)d_in[12];
    const float* W2vs = (const float*)d_in[13];
    const float* W2vvs = (const float*)d_in[14];
    const float* W2vvv = (const float*)d_in[15];
    const float* Lms = (const float*)d_in[16];
    const float* Lmv = (const float*)d_in[17];
    const float* W3ss = (const float*)d_in[18];
    const float* W3sv = (const float*)d_in[19];
    const float* W3vs = (const float*)d_in[20];
    const float* W3vvs = (const float*)d_in[21];
    const float* W3vvv = (const float*)d_in[22];
    const float* Lus = (const float*)d_in[23];
    const float* Luv = (const float*)d_in[24];
    float* out = (float*)d_out;

    int N = in_sizes[0] / 16;
    int E = in_sizes[3] / 8;
    int gE = (E + 127) / 128;
    int gG = (E + 63) / 64;
    int gN = (N + 127) / 128;

    zero_kernel<<<(N * 80 + 255) / 256, 256>>>(N * 80);
    stage1_s_kernel<<<gE, 128>>>(node_s, node_v, eidx, W1ss, W1vvs, E);
    stage1_v_kernel<<<gE, 128>>>(node_s, node_v, eidx, W1sv, W1vs, W1vvv, E);
    stage2_prep_kernel<<<gE, 128>>>(edge_s, edge_v, E);
    stage2_gemm_kernel<<<gG, GT>>>(eidx, W2ss, W2vvs, E);
    stage2_v_kernel<<<gE, 128>>>(edge_s, edge_v, eidx, W2sv, W2vs, W2vvv, E);
    fold_kernel<<<(N + 255) / 256, 256>>>(Lms, Lmv, N);
    update_s_kernel<<<gN, 128>>>(node_s, node_v, W3ss, W3vvs, N);
    update_v_kernel<<<gN, 128>>>(node_s, node_v, W3sv, W3vs, W3vvv, N);
    final_kernel<<<(N + 255) / 256, 256>>>(Lus, Luv, out, N);
}

// round 10
// speedup vs baseline: 1.1684x; 1.1684x over previous
#include <cuda_runtime.h>

// ---------------- scratch (sizes fixed: N=50000, E=400000) ----------------
__device__ float g_agg [50048  * 80];   // per-node gated sums: 32 silu'd scalars + 48 vec comps
__device__ float g_agg2[50048  * 40];   // after Lms/Lmv fold: 16 s + 24 v
__device__ float g_mid [400000 * 40];   // stage-1 per-edge intermediate (e-major)
__device__ float g_gate[16 * 400000];   // sigmoid gates, t-major [16][E]
__device__ float g_hid [48 * 50048];    // update hidden scalars (silu'd / sigm'd), t-major
__device__ float g_hidv[48 * 50048];    // update gated vector comps, (k*3+c)-major

#define I2f   0.70710678118654752f
#define I3f   0.57735026918962576f
#define R128f 0.08838834764831845f
#define R32f  0.17677669529663687f

__device__ __forceinline__ float sigm_f(float x) {
    return __fdividef(1.f, 1.f + __expf(-x));
}

__device__ __forceinline__ void wload(float* __restrict__ dst, const float* __restrict__ src,
                                      int nf4, float sc, int tid, int nt) {
    for (int t = tid; t < nf4; t += nt) {
        float4 v = reinterpret_cast<const float4*>(src)[t];
        v.x *= sc; v.y *= sc; v.z *= sc; v.w *= sc;
        reinterpret_cast<float4*>(dst)[t] = v;
    }
}
__device__ __forceinline__ void wslice(float* __restrict__ dst, const float* __restrict__ src,
                                       int rows, int srcF4, int dstF4, int off4,
                                       float sc, int tid) {
    int n = rows * dstF4;
    for (int t = tid; t < n; t += 128) {
        int r = t / dstF4, o = t - r * dstF4;
        float4 v = reinterpret_cast<const float4*>(src)[r * srcF4 + off4 + o];
        v.x *= sc; v.y *= sc; v.z *= sc; v.w *= sc;
        reinterpret_cast<float4*>(dst)[t] = v;
    }
}
template<int K4>
__device__ __forceinline__ void fma_k(float* acc, const float* __restrict__ w, float p) {
#pragma unroll
    for (int k = 0; k < K4; k++) {
        float4 ww = reinterpret_cast<const float4*>(w)[k];
        acc[4 * k + 0] += p * ww.x; acc[4 * k + 1] += p * ww.y;
        acc[4 * k + 2] += p * ww.z; acc[4 * k + 3] += p * ww.w;
    }
}
__device__ __forceinline__ void fma_vo8(float* vo, const float* A, float bx, float by, float bz) {
#pragma unroll
    for (int k = 0; k < 8; k++) {
        vo[3 * k + 0] += A[k] * bx; vo[3 * k + 1] += A[k] * by; vo[3 * k + 2] += A[k] * bz;
    }
}
__device__ __forceinline__ void fma_cross8(float* vo, const float* __restrict__ w,
                                           float cx, float cy, float cz) {
#pragma unroll
    for (int q = 0; q < 2; q++) {
        float4 ww = reinterpret_cast<const float4*>(w)[q];
        vo[12 * q + 0]  += cx * ww.x; vo[12 * q + 1]  += cy * ww.x; vo[12 * q + 2]  += cz * ww.x;
        vo[12 * q + 3]  += cx * ww.y; vo[12 * q + 4]  += cy * ww.y; vo[12 * q + 5]  += cz * ww.y;
        vo[12 * q + 6]  += cx * ww.z; vo[12 * q + 7]  += cy * ww.z; vo[12 * q + 8]  += cz * ww.z;
        vo[12 * q + 9]  += cx * ww.w; vo[12 * q + 10] += cy * ww.w; vo[12 * q + 11] += cz * ww.w;
    }
}
__device__ __forceinline__ void ld_f(float* dst, const float* __restrict__ src, int nf4) {
#pragma unroll
    for (int q = 0; q < 6; q++)
        if (q < nf4) reinterpret_cast<float4*>(dst)[q] =
            __ldg(reinterpret_cast<const float4*>(src) + q);
}

// ---------------- kernels ----------------
__global__ void zero_kernel(int n) {
    int i = blockIdx.x * 256 + threadIdx.x;
    if (i < n) g_agg[i] = 0.f;
}

// stage1 scalar paths: ms[16] -> g_mid[e][0:16)
__global__ __launch_bounds__(128, 6) void stage1_s_kernel(
    const float* __restrict__ ns, const float* __restrict__ nv,
    const int* __restrict__ eidx,
    const float* __restrict__ W1ss, const float* __restrict__ W1vvs, int E)
{
    __shared__ float wss[4096], wd[1024];
    int tid = threadIdx.x;
    wload(wss, W1ss, 1024, I2f / 16.f, tid, 128);
    wload(wd, W1vvs, 256, I2f * I3f / 8.f, tid, 128);
    __syncthreads();
    int e = blockIdx.x * 128 + tid;
    if (e >= E) return;
    int r = eidx[e], c = eidx[E + e];

    float acc[16];
#pragma unroll
    for (int k = 0; k < 16; k++) acc[k] = 0.f;
    {
        float s1[16], s2[16];
        ld_f(s1, ns + (size_t)r * 16, 4);
        ld_f(s2, ns + (size_t)c * 16, 4);
#pragma unroll 1
        for (int i = 0; i < 16; i++) {
            float a = s1[i];
#pragma unroll 2
            for (int j = 0; j < 16; j++)
                fma_k<4>(acc, &wss[(i * 16 + j) * 16], a * s2[j]);
        }
    }
    {
        float v1[24], v2[24];
        ld_f(v1, nv + (size_t)r * 24, 6);
        ld_f(v2, nv + (size_t)c * 24, 6);
#pragma unroll 1
        for (int i = 0; i < 8; i++) {
            float ax = v1[3 * i], ay = v1[3 * i + 1], az = v1[3 * i + 2];
#pragma unroll 2
            for (int j = 0; j < 8; j++) {
                float d = ax * v2[3 * j] + ay * v2[3 * j + 1] + az * v2[3 * j + 2];
                fma_k<4>(acc, &wd[(i * 8 + j) * 16], d);
            }
        }
    }
    float* o = &g_mid[(size_t)e * 40];
#pragma unroll
    for (int q = 0; q < 4; q++)
        reinterpret_cast<float4*>(o)[q] = reinterpret_cast<float4*>(acc)[q];
}

// stage1 vector paths: mv[8][3] -> g_mid[e][16:40)
__global__ __launch_bounds__(128, 6) void stage1_v_kernel(
    const float* __restrict__ ns, const float* __restrict__ nv,
    const int* __restrict__ eidx,
    const float* __restrict__ W1sv, const float* __restrict__ W1vs,
    const float* __restrict__ W1vvv, int E)
{
    __shared__ float wsv[1024], wvs[1024], wvvv[512];
    int tid = threadIdx.x;
    wload(wsv, W1sv, 256, I3f * R128f, tid, 128);
    wload(wvs, W1vs, 256, I3f * R128f, tid, 128);
    wload(wvvv, W1vvv, 128, I2f * I3f / 8.f, tid, 128);
    __syncthreads();
    int e = blockIdx.x * 128 + tid;
    if (e >= E) return;
    int r = eidx[e], c = eidx[E + e];

    float vo[24];
#pragma unroll
    for (int k = 0; k < 24; k++) vo[k] = 0.f;
    float v2[24];
    ld_f(v2, nv + (size_t)c * 24, 6);
    {   // 0x1 -> 1
        float s1[16];
        ld_f(s1, ns + (size_t)r * 16, 4);
#pragma unroll 1
        for (int j = 0; j < 8; j++) {
            float A[8];
#pragma unroll
            for (int k = 0; k < 8; k++) A[k] = 0.f;
#pragma unroll 2
            for (int i = 0; i < 16; i++)
                fma_k<2>(A, &wsv[(i * 8 + j) * 8], s1[i]);
            fma_vo8(vo, A, v2[3 * j], v2[3 * j + 1], v2[3 * j + 2]);
        }
    }
    float v1[24];
    ld_f(v1, nv + (size_t)r * 24, 6);
    {   // 1x0 -> 1
        float s2[16];
        ld_f(s2, ns + (size_t)c * 16, 4);
#pragma unroll 1
        for (int i = 0; i < 8; i++) {
            float A[8];
#pragma unroll
            for (int k = 0; k < 8; k++) A[k] = 0.f;
#pragma unroll 2
            for (int j = 0; j < 16; j++)
                fma_k<2>(A, &wvs[(i * 16 + j) * 8], s2[j]);
            fma_vo8(vo, A, v1[3 * i], v1[3 * i + 1], v1[3 * i + 2]);
        }
    }
    // 1x1 -> 1
#pragma unroll 1
    for (int i = 0; i < 8; i++) {
        float ax = v1[3 * i], ay = v1[3 * i + 1], az = v1[3 * i + 2];
#pragma unroll 1
        for (int j = 0; j < 8; j++) {
            float bx = v2[3 * j], by = v2[3 * j + 1], bz = v2[3 * j + 2];
            fma_cross8(vo, &wvvv[(i * 8 + j) * 8],
                       ay * bz - az * by, az * bx - ax * bz, ax * by - ay * bx);
        }
    }
    float* o = &g_mid[(size_t)e * 40 + 16];
#pragma unroll
    for (int q = 0; q < 6; q++)
        reinterpret_cast<float4*>(o)[q] = reinterpret_cast<float4*>(vo)[q];
}

// ---- stage2 scalar path: FUSED tile GEMM (no global F) ----
// inp rows: 0-15 ms, 16-39 mv, 40-47 es, 48-71 ev.  C[128 edges][48] = F[192] x W[192][48]
#define S2T 192
#define EPAD 130
__global__ __launch_bounds__(S2T) void stage2_fused_kernel(
    const float* __restrict__ edge_s, const float* __restrict__ edge_v,
    const int* __restrict__ eidx,
    const float* __restrict__ W2ss, const float* __restrict__ W2vvs, int E)
{
    __shared__ float inp[72][EPAD];   // 37440 B
    __shared__ float Fs[16][128];     // 8192 B
    __shared__ float Ws[16][48];      // 3072 B  -> 48704 B total
    int tid = threadIdx.x;
    int e0 = blockIdx.x * 128;

    // stage inputs: 128 edges x 18 float4s, transposed into inp
    for (int t = tid; t < 128 * 18; t += S2T) {
        int el = t / 18, r4 = t % 18;
        int e = e0 + el;
        float4 v = make_float4(0.f, 0.f, 0.f, 0.f);
        if (e < E) {
            if (r4 < 10)      v = __ldg(reinterpret_cast<const float4*>(&g_mid[(size_t)e * 40]) + r4);
            else if (r4 < 12) v = __ldg(reinterpret_cast<const float4*>(edge_s + (size_t)e * 8) + (r4 - 10));
            else              v = __ldg(reinterpret_cast<const float4*>(edge_v + (size_t)e * 24) + (r4 - 12));
        }
        int r = r4 * 4;
        inp[r + 0][el] = v.x; inp[r + 1][el] = v.y;
        inp[r + 2][el] = v.z; inp[r + 3][el] = v.w;
    }

    int egrp = tid & 15;     // 16 groups x 8 edges
    int kgrp = tid >> 4;     // 12 groups x 4 k
    float acc[8][4];
#pragma unroll
    for (int a = 0; a < 8; a++)
#pragma unroll
        for (int b = 0; b < 4; b++) acc[a][b] = 0.f;

#pragma unroll 1
    for (int ch = 0; ch < 12; ch++) {
        __syncthreads();
        // W chunk (scaled)
        for (int t = tid; t < 16 * 48; t += S2T) {
            int r = t / 48, k = t - r * 48;
            int f = ch * 16 + r;
            Ws[r][k] = (f < 128) ? W2ss[f * 48 + k] * (I2f * R128f)
                                 : W2vvs[(f - 128) * 48 + k] * (I2f * I3f / 8.f);
        }
        // F chunk from inp
        if (ch < 8) {   // scalar-product features: f = i*8+j
            for (int t = tid; t < 16 * 128; t += S2T) {
                int r = t >> 7, e = t & 127;
                int f = ch * 16 + r;
                int i = f >> 3, j = f & 7;
                Fs[r][e] = inp[i][e] * inp[40 + j][e];
            }
        } else {        // dot features: fd = i*8+j
            for (int t = tid; t < 16 * 128; t += S2T) {
                int r = t >> 7, e = t & 127;
                int fd = (ch - 8) * 16 + r;
                int i = fd >> 3, j = fd & 7;
                int mr = 16 + 3 * i, er = 48 + 3 * j;
                Fs[r][e] = inp[mr][e] * inp[er][e]
                         + inp[mr + 1][e] * inp[er + 1][e]
                         + inp[mr + 2][e] * inp[er + 2][e];
            }
        }
        __syncthreads();
#pragma unroll
        for (int f = 0; f < 16; f++) {
            float4 fa = *reinterpret_cast<const float4*>(&Fs[f][egrp * 8]);
            float4 fb = *reinterpret_cast<const float4*>(&Fs[f][egrp * 8 + 4]);
            float4 w  = *reinterpret_cast<const float4*>(&Ws[f][kgrp * 4]);
            acc[0][0] += fa.x * w.x; acc[0][1] += fa.x * w.y; acc[0][2] += fa.x * w.z; acc[0][3] += fa.x * w.w;
            acc[1][0] += fa.y * w.x; acc[1][1] += fa.y * w.y; acc[1][2] += fa.y * w.z; acc[1][3] += fa.y * w.w;
            acc[2][0] += fa.z * w.x; acc[2][1] += fa.z * w.y; acc[2][2] += fa.z * w.z; acc[2][3] += fa.z * w.w;
            acc[3][0] += fa.w * w.x; acc[3][1] += fa.w * w.y; acc[3][2] += fa.w * w.z; acc[3][3] += fa.w * w.w;
            acc[4][0] += fb.x * w.x; acc[4][1] += fb.x * w.y; acc[4][2] += fb.x * w.z; acc[4][3] += fb.x * w.w;
            acc[5][0] += fb.y * w.x; acc[5][1] += fb.y * w.y; acc[5][2] += fb.y * w.z; acc[5][3] += fb.y * w.w;
            acc[6][0] += fb.z * w.x; acc[6][1] += fb.z * w.y; acc[6][2] += fb.z * w.z; acc[6][3] += fb.z * w.w;
            acc[7][0] += fb.w * w.x; acc[7][1] += fb.w * w.y; acc[7][2] += fb.w * w.z; acc[7][3] += fb.w * w.w;
        }
    }
    // epilogue: k<32 silu->atomic agg; k>=32 sigm->gate
    int kbase = kgrp * 4;
#pragma unroll 1
    for (int a = 0; a < 8; a++) {
        int e = e0 + egrp * 8 + a;
        if (e >= E) continue;
        if (kbase < 32) {
            int c = __ldg(eidx + E + e);
            float* dst = &g_agg[(size_t)c * 80 + kbase];
#pragma unroll
            for (int b = 0; b < 4; b++) {
                float v = acc[a][b];
                atomicAdd(dst + b, v * sigm_f(v));
            }
        } else {
#pragma unroll
            for (int b = 0; b < 4; b++) {
                float v = acc[a][b];
                g_gate[(size_t)(kbase - 32 + b) * E + e] = sigm_f(v);
            }
        }
    }
}

// stage2 vector paths, 2 k-chunks of 8. gate from g_gate, atomic into agg vec slots.
__global__ __launch_bounds__(128, 5) void stage2_v_kernel(
    const float* __restrict__ edge_s, const float* __restrict__ edge_v,
    const int* __restrict__ eidx,
    const float* __restrict__ W2sv, const float* __restrict__ W2vs,
    const float* __restrict__ W2vvv, int E)
{
    __shared__ float wsv[1024], wvs[1024], wvvv[512];
    int tid = threadIdx.x;
    int e = blockIdx.x * 128 + tid;
    bool act = e < E;
    int c = 0;
    float ms[16], mv[24], es[8], ev[24];
    if (act) {
        c = eidx[E + e];
        const float* m = &g_mid[(size_t)e * 40];
#pragma unroll
        for (int q = 0; q < 4; q++) reinterpret_cast<float4*>(ms)[q] = reinterpret_cast<const float4*>(m)[q];
#pragma unroll
        for (int q = 0; q < 6; q++) reinterpret_cast<float4*>(mv)[q] = reinterpret_cast<const float4*>(m)[4 + q];
        ld_f(es, edge_s + (size_t)e * 8, 2);
        ld_f(ev, edge_v + (size_t)e * 24, 6);
    }
#pragma unroll 1
    for (int ch = 0; ch < 2; ch++) {
        __syncthreads();
        wslice(wsv, W2sv, 128, 4, 2, ch * 2, I3f * R128f, tid);
        wslice(wvs, W2vs, 64, 4, 2, ch * 2, I3f / 8.f, tid);
        wslice(wvvv, W2vvv, 64, 4, 2, ch * 2, I2f * I3f / 8.f, tid);
        __syncthreads();
        if (!act) continue;
        float vo[24];
#pragma unroll
        for (int k = 0; k < 24; k++) vo[k] = 0.f;
#pragma unroll 1
        for (int j = 0; j < 8; j++) {
            float A[8];
#pragma unroll
            for (int k = 0; k < 8; k++) A[k] = 0.f;
#pragma unroll 2
            for (int i = 0; i < 16; i++)
                fma_k<2>(A, &wsv[(i * 8 + j) * 8], ms[i]);
            fma_vo8(vo, A, ev[3 * j], ev[3 * j + 1], ev[3 * j + 2]);
        }
#pragma unroll 1
        for (int i = 0; i < 8; i++) {
            float A[8];
#pragma unroll
            for (int k = 0; k < 8; k++) A[k] = 0.f;
#pragma unroll 2
            for (int j = 0; j < 8; j++)
                fma_k<2>(A, &wvs[(i * 8 + j) * 8], es[j]);
            fma_vo8(vo, A, mv[3 * i], mv[3 * i + 1], mv[3 * i + 2]);
        }
#pragma unroll 1
        for (int i = 0; i < 8; i++) {
            float ax = mv[3 * i], ay = mv[3 * i + 1], az = mv[3 * i + 2];
#pragma unroll 1
            for (int j = 0; j < 8; j++) {
                float bx = ev[3 * j], by = ev[3 * j + 1], bz = ev[3 * j + 2];
                fma_cross8(vo, &wvvv[(i * 8 + j) * 8],
                           ay * bz - az * by, az * bx - ax * bz, ax * by - ay * bx);
            }
        }
#pragma unroll
        for (int t = 0; t < 8; t++) {
            float g = g_gate[(size_t)(ch * 8 + t) * E + e];
            float* dst = &g_agg[(size_t)c * 80 + 32 + (ch * 8 + t) * 3];
            atomicAdd(dst + 0, vo[3 * t + 0] * g);
            atomicAdd(dst + 1, vo[3 * t + 1] * g);
            atomicAdd(dst + 2, vo[3 * t + 2] * g);
        }
    }
}

// fold Lms/Lmv into aggregated (post-gate) sums: g_agg[N,80] -> g_agg2[N,40]
__global__ void fold_kernel(const float* __restrict__ Lms, const float* __restrict__ Lmv, int N)
{
    __shared__ float lms[512], lmv[128];
    int tid = threadIdx.x;
    wload(lms, Lms, 128, R32f, tid, 256);
    wload(lmv, Lmv, 32, 0.25f, tid, 256);
    __syncthreads();
    int n = blockIdx.x * 256 + tid;
    if (n >= N) return;
    const float* a = &g_agg[(size_t)n * 80];
    float* o = &g_agg2[(size_t)n * 40];
    float os[16];
#pragma unroll
    for (int k = 0; k < 16; k++) os[k] = 0.f;
#pragma unroll 1
    for (int i = 0; i < 32; i++)
        fma_k<4>(os, &lms[i * 16], a[i]);
#pragma unroll
    for (int k = 0; k < 16; k++) o[k] = os[k];
    float ov[24];
#pragma unroll
    for (int k = 0; k < 24; k++) ov[k] = 0.f;
#pragma unroll 1
    for (int i = 0; i < 16; i++) {
        float ax = a[32 + 3 * i], ay = a[32 + 3 * i + 1], az = a[32 + 3 * i + 2];
        const float* w = &lmv[i * 8];
#pragma unroll
        for (int k = 0; k < 8; k++) {
            float ww = w[k];
            ov[3 * k + 0] += ax * ww; ov[3 * k + 1] += ay * ww; ov[3 * k + 2] += az * ww;
        }
    }
#pragma unroll
    for (int t = 0; t < 24; t++) o[16 + t] = ov[t];
}

// update scalar paths -> g_hid (silu'd for k<32, sigm'd for k>=32)
__global__ __launch_bounds__(128, 5) void update_s_kernel(
    const float* __restrict__ ns, const float* __restrict__ nv,
    const float* __restrict__ W3ss, const float* __restrict__ W3vvs, int N)
{
    __shared__ float ws[4096], wd[1024];
    int tid = threadIdx.x;
    int n = blockIdx.x * 128 + tid;
    bool act = n < N;
    float s1[16], v1[24], s2[16], v2[24];
    if (act) {
        ld_f(s1, ns + (size_t)n * 16, 4);
        ld_f(v1, nv + (size_t)n * 24, 6);
        const float* a = &g_agg2[(size_t)n * 40];
#pragma unroll
        for (int q = 0; q < 4; q++) reinterpret_cast<float4*>(s2)[q] = reinterpret_cast<const float4*>(a)[q];
#pragma unroll
        for (int q = 0; q < 6; q++) reinterpret_cast<float4*>(v2)[q] = reinterpret_cast<const float4*>(a)[4 + q];
    }
#pragma unroll 1
    for (int ch = 0; ch < 3; ch++) {
        __syncthreads();
        wslice(ws, W3ss, 256, 12, 4, ch * 4, I2f / 16.f, tid);
        wslice(wd, W3vvs, 64, 12, 4, ch * 4, I2f * I3f / 8.f, tid);
        __syncthreads();
        if (!act) continue;
        float acc[16];
#pragma unroll
        for (int k = 0; k < 16; k++) acc[k] = 0.f;
#pragma unroll 1
        for (int i = 0; i < 16; i++) {
            float a = s1[i];
#pragma unroll 2
            for (int j = 0; j < 16; j++)
                fma_k<4>(acc, &ws[(i * 16 + j) * 16], a * s2[j]);
        }
#pragma unroll 1
        for (int i = 0; i < 8; i++) {
            float ax = v1[3 * i], ay = v1[3 * i + 1], az = v1[3 * i + 2];
#pragma unroll 2
            for (int j = 0; j < 8; j++) {
                float d = ax * v2[3 * j] + ay * v2[3 * j + 1] + az * v2[3 * j + 2];
                fma_k<4>(acc, &wd[(i * 8 + j) * 16], d);
            }
        }
#pragma unroll
        for (int t = 0; t < 16; t++) {
            float v = (ch < 2) ? acc[t] * sigm_f(acc[t]) : sigm_f(acc[t]);
            g_hid[(size_t)(ch * 16 + t) * N + n] = v;
        }
    }
}

// update vector paths -> gated comps in g_hidv
__global__ __launch_bounds__(128, 5) void update_v_kernel(
    const float* __restrict__ ns, const float* __restrict__ nv,
    const float* __restrict__ W3sv, const float* __restrict__ W3vs,
    const float* __restrict__ W3vvv, int N)
{
    __shared__ float wsv[1024], wvs[1024], wvvv[512];
    int tid = threadIdx.x;
    int n = blockIdx.x * 128 + tid;
    bool act = n < N;
    float s1[16], v1[24], s2[16], v2[24];
    if (act) {
        ld_f(s1, ns + (size_t)n * 16, 4);
        ld_f(v1, nv + (size_t)n * 24, 6);
        const float* a = &g_agg2[(size_t)n * 40];
#pragma unroll
        for (int q = 0; q < 4; q++) reinterpret_cast<float4*>(s2)[q] = reinterpret_cast<const float4*>(a)[q];
#pragma unroll
        for (int q = 0; q < 6; q++) reinterpret_cast<float4*>(v2)[q] = reinterpret_cast<const float4*>(a)[4 + q];
    }
#pragma unroll 1
    for (int ch = 0; ch < 2; ch++) {
        __syncthreads();
        wslice(wsv, W3sv, 128, 4, 2, ch * 2, I3f * R128f, tid);
        wslice(wvs, W3vs, 128, 4, 2, ch * 2, I3f * R128f, tid);
        wslice(wvvv, W3vvv, 64, 4, 2, ch * 2, I2f * I3f / 8.f, tid);
        __syncthreads();
        if (!act) continue;
        float vo[24];
#pragma unroll
        for (int k = 0; k < 24; k++) vo[k] = 0.f;
#pragma unroll 1
        for (int j = 0; j < 8; j++) {
            float A[8];
#pragma unroll
            for (int k = 0; k < 8; k++) A[k] = 0.f;
#pragma unroll 2
            for (int i = 0; i < 16; i++)
                fma_k<2>(A, &wsv[(i * 8 + j) * 8], s1[i]);
            fma_vo8(vo, A, v2[3 * j], v2[3 * j + 1], v2[3 * j + 2]);
        }
#pragma unroll 1
        for (int i = 0; i < 8; i++) {
            float A[8];
#pragma unroll
            for (int k = 0; k < 8; k++) A[k] = 0.f;
#pragma unroll 2
            for (int j = 0; j < 16; j++)
                fma_k<2>(A, &wvs[(i * 16 + j) * 8], s2[j]);
            fma_vo8(vo, A, v1[3 * i], v1[3 * i + 1], v1[3 * i + 2]);
        }
#pragma unroll 1
        for (int i = 0; i < 8; i++) {
            float ax = v1[3 * i], ay = v1[3 * i + 1], az = v1[3 * i + 2];
#pragma unroll 1
            for (int j = 0; j < 8; j++) {
                float bx = v2[3 * j], by = v2[3 * j + 1], bz = v2[3 * j + 2];
                float cx = ay * bz - az * by, cy = az * bx - ax * bz, cz = ax * by - ay * bx;
                fma_cross8(vo, &wvvv[(i * 8 + j) * 8], cx, cy, cz);
            }
        }
#pragma unroll
        for (int t = 0; t < 8; t++) {
            float g = g_hid[(size_t)(32 + ch * 8 + t) * N + n];
#pragma unroll
            for (int cc = 0; cc < 3; cc++)
                g_hidv[(size_t)((ch * 8 + t) * 3 + cc) * N + n] = vo[3 * t + cc] * g;
        }
    }
}

// final: apply Lus/Luv per node, write out[N,40]
__global__ void final_kernel(const float* __restrict__ Lus, const float* __restrict__ Luv,
                             float* __restrict__ out, int N)
{
    __shared__ float lus[512], luv[128];
    int tid = threadIdx.x;
    wload(lus, Lus, 128, R32f, tid, 256);
    wload(luv, Luv, 32, 0.25f, tid, 256);
    __syncthreads();
    int n = blockIdx.x * 256 + tid;
    if (n >= N) return;
    float os[16];
#pragma unroll
    for (int k = 0; k < 16; k++) os[k] = 0.f;
#pragma unroll 1
    for (int i = 0; i < 32; i++)
        fma_k<4>(os, &lus[i * 16], g_hid[(size_t)i * N + n]);
    float ov[24];
#pragma unroll
    for (int k = 0; k < 24; k++) ov[k] = 0.f;
#pragma unroll 1
    for (int i = 0; i < 16; i++) {
        float ax = g_hidv[(size_t)(3 * i + 0) * N + n];
        float ay = g_hidv[(size_t)(3 * i + 1) * N + n];
        float az = g_hidv[(size_t)(3 * i + 2) * N + n];
        const float* w = &luv[i * 8];
#pragma unroll
        for (int k = 0; k < 8; k++) {
            float ww = w[k];
            ov[3 * k + 0] += ax * ww; ov[3 * k + 1] += ay * ww; ov[3 * k + 2] += az * ww;
        }
    }
    float* o = out + (size_t)n * 40;
#pragma unroll
    for (int k = 0; k < 16; k++) o[k] = os[k];
#pragma unroll
    for (int t = 0; t < 24; t++) o[16 + t] = ov[t];
}

// ---------------- launch ----------------
extern "C" void kernel_launch(void* const* d_in, const int* in_sizes, int n_in,
                              void* d_out, int out_size) {
    const float* node_s = (const float*)d_in[0];
    const float* node_v = (const float*)d_in[1];
    const float* edge_s = (const float*)d_in[3];
    const float* edge_v = (const float*)d_in[4];
    const int*   eidx   = (const int*)d_in[5];
    const float* W1ss = (const float*)d_in[6];
    const float* W1sv = (const float*)d_in[7];
    const float* W1vs = (const float*)d_in[8];
    const float* W1vvs = (const float*)d_in[9];
    const float* W1vvv = (const float*)d_in[10];
    const float* W2ss = (const float*)d_in[11];
    const float* W2sv = (const float*)d_in[12];
    const float* W2vs = (const float*)d_in[13];
    const float* W2vvs = (const float*)d_in[14];
    const float* W2vvv = (const float*)d_in[15];
    const float* Lms = (const float*)d_in[16];
    const float* Lmv = (const float*)d_in[17];
    const float* W3ss = (const float*)d_in[18];
    const float* W3sv = (const float*)d_in[19];
    const float* W3vs = (const float*)d_in[20];
    const float* W3vvs = (const float*)d_in[21];
    const float* W3vvv = (const float*)d_in[22];
    const float* Lus = (const float*)d_in[23];
    const float* Luv = (const float*)d_in[24];
    float* out = (float*)d_out;

    int N = in_sizes[0] / 16;
    int E = in_sizes[3] / 8;
    int gE = (E + 127) / 128;
    int gN = (N + 127) / 128;

    zero_kernel<<<(N * 80 + 255) / 256, 256>>>(N * 80);
    stage1_s_kernel<<<gE, 128>>>(node_s, node_v, eidx, W1ss, W1vvs, E);
    stage1_v_kernel<<<gE, 128>>>(node_s, node_v, eidx, W1sv, W1vs, W1vvv, E);
    stage2_fused_kernel<<<gE, S2T>>>(edge_s, edge_v, eidx, W2ss, W2vvs, E);
    stage2_v_kernel<<<gE, 128>>>(edge_s, edge_v, eidx, W2sv, W2vs, W2vvv, E);
    fold_kernel<<<(N + 255) / 256, 256>>>(Lms, Lmv, N);
    update_s_kernel<<<gN, 128>>>(node_s, node_v, W3ss, W3vvs, N);
    update_v_kernel<<<gN, 128>>>(node_s, node_v, W3sv, W3vs, W3vvv, N);
    final_kernel<<<(N + 255) / 256, 256>>>(Lus, Luv, out, N);
}

// round 12
// speedup vs baseline: 1.3077x; 1.1192x over previous
#include <cuda_runtime.h>

// ---------------- scratch (sizes fixed: N=50000, E=400000) ----------------
__device__ float g_agg [50048  * 80];   // per-node gated sums: 32 silu'd scalars + 48 vec comps
__device__ float g_agg2[50048  * 40];   // after Lms/Lmv fold: 16 s + 24 v
__device__ float g_mid [400000 * 40];   // stage-1 per-edge intermediate (e-major)

#define I2f   0.70710678118654752f
#define I3f   0.57735026918962576f
#define R128f 0.08838834764831845f
#define R32f  0.17677669529663687f

__device__ __forceinline__ float sigm_f(float x) {
    return __fdividef(1.f, 1.f + __expf(-x));
}

__device__ __forceinline__ void wload(float* __restrict__ dst, const float* __restrict__ src,
                                      int nf4, float sc, int tid, int nt) {
    for (int t = tid; t < nf4; t += nt) {
        float4 v = reinterpret_cast<const float4*>(src)[t];
        v.x *= sc; v.y *= sc; v.z *= sc; v.w *= sc;
        reinterpret_cast<float4*>(dst)[t] = v;
    }
}
__device__ __forceinline__ void wslice(float* __restrict__ dst, const float* __restrict__ src,
                                       int rows, int srcF4, int dstF4, int off4,
                                       float sc, int tid) {
    int n = rows * dstF4;
    for (int t = tid; t < n; t += 128) {
        int r = t / dstF4, o = t - r * dstF4;
        float4 v = reinterpret_cast<const float4*>(src)[r * srcF4 + off4 + o];
        v.x *= sc; v.y *= sc; v.z *= sc; v.w *= sc;
        reinterpret_cast<float4*>(dst)[t] = v;
    }
}
template<int K4>
__device__ __forceinline__ void fma_k(float* acc, const float* __restrict__ w, float p) {
#pragma unroll
    for (int k = 0; k < K4; k++) {
        float4 ww = reinterpret_cast<const float4*>(w)[k];
        acc[4 * k + 0] += p * ww.x; acc[4 * k + 1] += p * ww.y;
        acc[4 * k + 2] += p * ww.z; acc[4 * k + 3] += p * ww.w;
    }
}
__device__ __forceinline__ void fma_vo8(float* vo, const float* A, float bx, float by, float bz) {
#pragma unroll
    for (int k = 0; k < 8; k++) {
        vo[3 * k + 0] += A[k] * bx; vo[3 * k + 1] += A[k] * by; vo[3 * k + 2] += A[k] * bz;
    }
}
__device__ __forceinline__ void fma_cross8(float* vo, const float* __restrict__ w,
                                           float cx, float cy, float cz) {
#pragma unroll
    for (int q = 0; q < 2; q++) {
        float4 ww = reinterpret_cast<const float4*>(w)[q];
        vo[12 * q + 0]  += cx * ww.x; vo[12 * q + 1]  += cy * ww.x; vo[12 * q + 2]  += cz * ww.x;
        vo[12 * q + 3]  += cx * ww.y; vo[12 * q + 4]  += cy * ww.y; vo[12 * q + 5]  += cz * ww.y;
        vo[12 * q + 6]  += cx * ww.z; vo[12 * q + 7]  += cy * ww.z; vo[12 * q + 8]  += cz * ww.z;
        vo[12 * q + 9]  += cx * ww.w; vo[12 * q + 10] += cy * ww.w; vo[12 * q + 11] += cz * ww.w;
    }
}
__device__ __forceinline__ void ld_f(float* dst, const float* __restrict__ src, int nf4) {
#pragma unroll
    for (int q = 0; q < 6; q++)
        if (q < nf4) reinterpret_cast<float4*>(dst)[q] =
            __ldg(reinterpret_cast<const float4*>(src) + q);
}

// ---------------- kernels ----------------
__global__ void zero_kernel(int n) {
    int i = blockIdx.x * 256 + threadIdx.x;
    if (i < n) g_agg[i] = 0.f;
}

// stage1 fused: all 5 paths per edge, inputs gathered once -> g_mid[e][0:40)
__global__ __launch_bounds__(128, 4) void stage1_kernel(
    const float* __restrict__ ns, const float* __restrict__ nv,
    const int* __restrict__ eidx,
    const float* __restrict__ W1ss, const float* __restrict__ W1sv,
    const float* __restrict__ W1vs, const float* __restrict__ W1vvs,
    const float* __restrict__ W1vvv, int E)
{
    __shared__ float wss[4096], wvvs[1024], wsv[1024], wvs[1024], wvvv[512];
    int tid = threadIdx.x;
    wload(wss,  W1ss,  1024, I2f / 16.f,     tid, 128);
    wload(wvvs, W1vvs,  256, I2f * I3f / 8.f, tid, 128);
    wload(wsv,  W1sv,   256, I3f * R128f,    tid, 128);
    wload(wvs,  W1vs,   256, I3f * R128f,    tid, 128);
    wload(wvvv, W1vvv,  128, I2f * I3f / 8.f, tid, 128);
    __syncthreads();
    int e = blockIdx.x * 128 + tid;
    if (e >= E) return;
    int r = eidx[e], c = eidx[E + e];

    float s1[16], s2[16], v1[24], v2[24];
    ld_f(s1, ns + (size_t)r * 16, 4);
    ld_f(s2, ns + (size_t)c * 16, 4);
    ld_f(v1, nv + (size_t)r * 24, 6);
    ld_f(v2, nv + (size_t)c * 24, 6);

    // ---- scalar paths ----
    {
        float acc[16];
#pragma unroll
        for (int k = 0; k < 16; k++) acc[k] = 0.f;
#pragma unroll 1
        for (int i = 0; i < 16; i++) {
            float a = s1[i];
#pragma unroll 2
            for (int j = 0; j < 16; j++)
                fma_k<4>(acc, &wss[(i * 16 + j) * 16], a * s2[j]);
        }
#pragma unroll 1
        for (int i = 0; i < 8; i++) {
            float ax = v1[3 * i], ay = v1[3 * i + 1], az = v1[3 * i + 2];
#pragma unroll 2
            for (int j = 0; j < 8; j++) {
                float d = ax * v2[3 * j] + ay * v2[3 * j + 1] + az * v2[3 * j + 2];
                fma_k<4>(acc, &wvvs[(i * 8 + j) * 16], d);
            }
        }
        float* o = &g_mid[(size_t)e * 40];
#pragma unroll
        for (int q = 0; q < 4; q++)
            reinterpret_cast<float4*>(o)[q] = reinterpret_cast<float4*>(acc)[q];
    }
    // ---- vector paths ----
    {
        float vo[24];
#pragma unroll
        for (int k = 0; k < 24; k++) vo[k] = 0.f;
#pragma unroll 1
        for (int j = 0; j < 8; j++) {
            float A[8];
#pragma unroll
            for (int k = 0; k < 8; k++) A[k] = 0.f;
#pragma unroll 2
            for (int i = 0; i < 16; i++)
                fma_k<2>(A, &wsv[(i * 8 + j) * 8], s1[i]);
            fma_vo8(vo, A, v2[3 * j], v2[3 * j + 1], v2[3 * j + 2]);
        }
#pragma unroll 1
        for (int i = 0; i < 8; i++) {
            float A[8];
#pragma unroll
            for (int k = 0; k < 8; k++) A[k] = 0.f;
#pragma unroll 2
            for (int j = 0; j < 16; j++)
                fma_k<2>(A, &wvs[(i * 16 + j) * 8], s2[j]);
            fma_vo8(vo, A, v1[3 * i], v1[3 * i + 1], v1[3 * i + 2]);
        }
#pragma unroll 1
        for (int i = 0; i < 8; i++) {
            float ax = v1[3 * i], ay = v1[3 * i + 1], az = v1[3 * i + 2];
#pragma unroll 1
            for (int j = 0; j < 8; j++) {
                float bx = v2[3 * j], by = v2[3 * j + 1], bz = v2[3 * j + 2];
                fma_cross8(vo, &wvvv[(i * 8 + j) * 8],
                           ay * bz - az * by, az * bx - ax * bz, ax * by - ay * bx);
            }
        }
        float* o = &g_mid[(size_t)e * 40 + 16];
#pragma unroll
        for (int q = 0; q < 6; q++)
            reinterpret_cast<float4*>(o)[q] = reinterpret_cast<float4*>(vo)[q];
    }
}

// stage2 fused: 3 scalar k-chunks (silu->atomic; gates->regs) then 2 vector k-chunks
// using register gates. g_gate eliminated.
__global__ __launch_bounds__(128, 4) void stage2_kernel(
    const float* __restrict__ edge_s, const float* __restrict__ edge_v,
    const int* __restrict__ eidx,
    const float* __restrict__ W2ss, const float* __restrict__ W2vvs,
    const float* __restrict__ W2sv, const float* __restrict__ W2vs,
    const float* __restrict__ W2vvv, int E)
{
    __shared__ float ws[2048], wd[1024];          // scalar chunk slices
    __shared__ float wsv[1024], wvs[512], wvvv[512]; // vector chunk slices
    int tid = threadIdx.x;
    int e = blockIdx.x * 128 + tid;
    bool act = e < E;
    int c = 0;
    float ms[16], mv[24], es[8], ev[24];
    if (act) {
        c = eidx[E + e];
        const float* m = &g_mid[(size_t)e * 40];
#pragma unroll
        for (int q = 0; q < 4; q++) reinterpret_cast<float4*>(ms)[q] = reinterpret_cast<const float4*>(m)[q];
#pragma unroll
        for (int q = 0; q < 6; q++) reinterpret_cast<float4*>(mv)[q] = reinterpret_cast<const float4*>(m)[4 + q];
        ld_f(es, edge_s + (size_t)e * 8, 2);
        ld_f(ev, edge_v + (size_t)e * 24, 6);
    }
    float gate[16];

    // ---- scalar chunks ----
#pragma unroll 1
    for (int ch = 0; ch < 3; ch++) {
        __syncthreads();
        wslice(ws, W2ss, 128, 12, 4, ch * 4, I2f * R128f, tid);
        wslice(wd, W2vvs, 64, 12, 4, ch * 4, I2f * I3f / 8.f, tid);
        __syncthreads();
        if (!act) continue;
        float acc[16];
#pragma unroll
        for (int k = 0; k < 16; k++) acc[k] = 0.f;
#pragma unroll 1
        for (int i = 0; i < 16; i++) {
            float a = ms[i];
#pragma unroll 2
            for (int j = 0; j < 8; j++)
                fma_k<4>(acc, &ws[(i * 8 + j) * 16], a * es[j]);
        }
#pragma unroll 1
        for (int i = 0; i < 8; i++) {
            float ax = mv[3 * i], ay = mv[3 * i + 1], az = mv[3 * i + 2];
#pragma unroll 2
            for (int j = 0; j < 8; j++) {
                float d = ax * ev[3 * j] + ay * ev[3 * j + 1] + az * ev[3 * j + 2];
                fma_k<4>(acc, &wd[(i * 8 + j) * 16], d);
            }
        }
        if (ch < 2) {
            float* dst = &g_agg[(size_t)c * 80 + ch * 16];
#pragma unroll
            for (int t = 0; t < 16; t++)
                atomicAdd(dst + t, acc[t] * sigm_f(acc[t]));   // silu
        } else {
#pragma unroll
            for (int t = 0; t < 16; t++)
                gate[t] = sigm_f(acc[t]);
        }
    }

    // ---- vector chunks (gates in registers) ----
#pragma unroll 1
    for (int ch = 0; ch < 2; ch++) {
        __syncthreads();
        wslice(wsv, W2sv, 128, 4, 2, ch * 2, I3f * R128f, tid);
        wslice(wvs, W2vs, 64, 4, 2, ch * 2, I3f / 8.f, tid);
        wslice(wvvv, W2vvv, 64, 4, 2, ch * 2, I2f * I3f / 8.f, tid);
        __syncthreads();
        if (!act) continue;
        float vo[24];
#pragma unroll
        for (int k = 0; k < 24; k++) vo[k] = 0.f;
#pragma unroll 1
        for (int j = 0; j < 8; j++) {
            float A[8];
#pragma unroll
            for (int k = 0; k < 8; k++) A[k] = 0.f;
#pragma unroll 2
            for (int i = 0; i < 16; i++)
                fma_k<2>(A, &wsv[(i * 8 + j) * 8], ms[i]);
            fma_vo8(vo, A, ev[3 * j], ev[3 * j + 1], ev[3 * j + 2]);
        }
#pragma unroll 1
        for (int i = 0; i < 8; i++) {
            float A[8];
#pragma unroll
            for (int k = 0; k < 8; k++) A[k] = 0.f;
#pragma unroll 2
            for (int j = 0; j < 8; j++)
                fma_k<2>(A, &wvs[(i * 8 + j) * 8], es[j]);
            fma_vo8(vo, A, mv[3 * i], mv[3 * i + 1], mv[3 * i + 2]);
        }
#pragma unroll 1
        for (int i = 0; i < 8; i++) {
            float ax = mv[3 * i], ay = mv[3 * i + 1], az = mv[3 * i + 2];
#pragma unroll 1
            for (int j = 0; j < 8; j++) {
                float bx = ev[3 * j], by = ev[3 * j + 1], bz = ev[3 * j + 2];
                fma_cross8(vo, &wvvv[(i * 8 + j) * 8],
                           ay * bz - az * by, az * bx - ax * bz, ax * by - ay * bx);
            }
        }
#pragma unroll
        for (int t = 0; t < 8; t++) {
            float g = gate[ch * 8 + t];
            float* dst = &g_agg[(size_t)c * 80 + 32 + (ch * 8 + t) * 3];
            atomicAdd(dst + 0, vo[3 * t + 0] * g);
            atomicAdd(dst + 1, vo[3 * t + 1] * g);
            atomicAdd(dst + 2, vo[3 * t + 2] * g);
        }
    }
}

// fold Lms/Lmv into aggregated (post-gate) sums: g_agg[N,80] -> g_agg2[N,40]
__global__ void fold_kernel(const float* __restrict__ Lms, const float* __restrict__ Lmv, int N)
{
    __shared__ float lms[512], lmv[128];
    int tid = threadIdx.x;
    wload(lms, Lms, 128, R32f, tid, 256);
    wload(lmv, Lmv, 32, 0.25f, tid, 256);
    __syncthreads();
    int n = blockIdx.x * 256 + tid;
    if (n >= N) return;
    const float* a = &g_agg[(size_t)n * 80];
    float* o = &g_agg2[(size_t)n * 40];
    float os[16];
#pragma unroll
    for (int k = 0; k < 16; k++) os[k] = 0.f;
#pragma unroll 1
    for (int i = 0; i < 32; i++)
        fma_k<4>(os, &lms[i * 16], a[i]);
#pragma unroll
    for (int k = 0; k < 16; k++) o[k] = os[k];
    float ov[24];
#pragma unroll
    for (int k = 0; k < 24; k++) ov[k] = 0.f;
#pragma unroll 1
    for (int i = 0; i < 16; i++) {
        float ax = a[32 + 3 * i], ay = a[32 + 3 * i + 1], az = a[32 + 3 * i + 2];
        const float* w = &lmv[i * 8];
#pragma unroll
        for (int k = 0; k < 8; k++) {
            float ww = w[k];
            ov[3 * k + 0] += ax * ww; ov[3 * k + 1] += ay * ww; ov[3 * k + 2] += az * ww;
        }
    }
#pragma unroll
    for (int t = 0; t < 24; t++) o[16 + t] = ov[t];
}

// update fused: scalar chunks (silu -> fold Lus into os; gates->regs), vector chunks
// (gate + fold Luv into ov), write out directly. g_hid/g_hidv/final eliminated.
__global__ __launch_bounds__(128, 4) void update_kernel(
    const float* __restrict__ ns, const float* __restrict__ nv,
    const float* __restrict__ W3ss, const float* __restrict__ W3vvs,
    const float* __restrict__ W3sv, const float* __restrict__ W3vs,
    const float* __restrict__ W3vvv,
    const float* __restrict__ Lus, const float* __restrict__ Luv,
    float* __restrict__ out, int N)
{
    __shared__ float ws[4096], wd[1024];            // scalar slices
    __shared__ float wsv[1024], wvs[1024], wvvv[512]; // vector slices
    __shared__ float lus[512], luv[128];
    int tid = threadIdx.x;
    wload(lus, Lus, 128, R32f, tid, 128);
    wload(luv, Luv, 32, 0.25f, tid, 128);
    int n = blockIdx.x * 128 + tid;
    bool act = n < N;
    float s1[16], v1[24], s2[16], v2[24];
    if (act) {
        ld_f(s1, ns + (size_t)n * 16, 4);
        ld_f(v1, nv + (size_t)n * 24, 6);
        const float* a = &g_agg2[(size_t)n * 40];
#pragma unroll
        for (int q = 0; q < 4; q++) reinterpret_cast<float4*>(s2)[q] = reinterpret_cast<const float4*>(a)[q];
#pragma unroll
        for (int q = 0; q < 6; q++) reinterpret_cast<float4*>(v2)[q] = reinterpret_cast<const float4*>(a)[4 + q];
    }
    float os[16], ov[24], gate[16];
#pragma unroll
    for (int k = 0; k < 16; k++) os[k] = 0.f;
#pragma unroll
    for (int k = 0; k < 24; k++) ov[k] = 0.f;

    // ---- scalar chunks ----
#pragma unroll 1
    for (int ch = 0; ch < 3; ch++) {
        __syncthreads();
        wslice(ws, W3ss, 256, 12, 4, ch * 4, I2f / 16.f, tid);
        wslice(wd, W3vvs, 64, 12, 4, ch * 4, I2f * I3f / 8.f, tid);
        __syncthreads();
        if (!act) continue;
        float acc[16];
#pragma unroll
        for (int k = 0; k < 16; k++) acc[k] = 0.f;
#pragma unroll 1
        for (int i = 0; i < 16; i++) {
            float a = s1[i];
#pragma unroll 2
            for (int j = 0; j < 16; j++)
                fma_k<4>(acc, &ws[(i * 16 + j) * 16], a * s2[j]);
        }
#pragma unroll 1
        for (int i = 0; i < 8; i++) {
            float ax = v1[3 * i], ay = v1[3 * i + 1], az = v1[3 * i + 2];
#pragma unroll 2
            for (int j = 0; j < 8; j++) {
                float d = ax * v2[3 * j] + ay * v2[3 * j + 1] + az * v2[3 * j + 2];
                fma_k<4>(acc, &wd[(i * 8 + j) * 16], d);
            }
        }
        if (ch < 2) {
#pragma unroll 1
            for (int t = 0; t < 16; t++) {
                float a = acc[t] * sigm_f(acc[t]);           // silu
                fma_k<4>(os, &lus[(ch * 16 + t) * 16], a);   // fold Lus
            }
        } else {
#pragma unroll
            for (int t = 0; t < 16; t++)
                gate[t] = sigm_f(acc[t]);
        }
    }

    // ---- vector chunks ----
#pragma unroll 1
    for (int ch = 0; ch < 2; ch++) {
        __syncthreads();
        wslice(wsv, W3sv, 128, 4, 2, ch * 2, I3f * R128f, tid);
        wslice(wvs, W3vs, 128, 4, 2, ch * 2, I3f * R128f, tid);
        wslice(wvvv, W3vvv, 64, 4, 2, ch * 2, I2f * I3f / 8.f, tid);
        __syncthreads();
        if (!act) continue;
        float vo[24];
#pragma unroll
        for (int k = 0; k < 24; k++) vo[k] = 0.f;
#pragma unroll 1
        for (int j = 0; j < 8; j++) {
            float A[8];
#pragma unroll
            for (int k = 0; k < 8; k++) A[k] = 0.f;
#pragma unroll 2
            for (int i = 0; i < 16; i++)
                fma_k<2>(A, &wsv[(i * 8 + j) * 8], s1[i]);
            fma_vo8(vo, A, v2[3 * j], v2[3 * j + 1], v2[3 * j + 2]);
        }
#pragma unroll 1
        for (int i = 0; i < 8; i++) {
            float A[8];
#pragma unroll
            for (int k = 0; k < 8; k++) A[k] = 0.f;
#pragma unroll 2
            for (int j = 0; j < 16; j++)
                fma_k<2>(A, &wvs[(i * 16 + j) * 8], s2[j]);
            fma_vo8(vo, A, v1[3 * i], v1[3 * i + 1], v1[3 * i + 2]);
        }
#pragma unroll 1
        for (int i = 0; i < 8; i++) {
            float ax = v1[3 * i], ay = v1[3 * i + 1], az = v1[3 * i + 2];
#pragma unroll 1
            for (int j = 0; j < 8; j++) {
                float bx = v2[3 * j], by = v2[3 * j + 1], bz = v2[3 * j + 2];
                float cx = ay * bz - az * by, cy = az * bx - ax * bz, cz = ax * by - ay * bx;
                fma_cross8(vo, &wvvv[(i * 8 + j) * 8], cx, cy, cz);
            }
        }
        // gate + fold Luv
#pragma unroll 1
        for (int t = 0; t < 8; t++) {
            float g = gate[ch * 8 + t];
            float gx = vo[3 * t + 0] * g, gy = vo[3 * t + 1] * g, gz = vo[3 * t + 2] * g;
            const float* w = &luv[(ch * 8 + t) * 8];
#pragma unroll
            for (int k = 0; k < 8; k++) {
                float ww = w[k];
                ov[3 * k + 0] += gx * ww; ov[3 * k + 1] += gy * ww; ov[3 * k + 2] += gz * ww;
            }
        }
    }
    if (act) {
        float* o = out + (size_t)n * 40;
#pragma unroll
        for (int q = 0; q < 4; q++) reinterpret_cast<float4*>(o)[q] = reinterpret_cast<float4*>(os)[q];
#pragma unroll
        for (int q = 0; q < 6; q++) reinterpret_cast<float4*>(o)[4 + q] = reinterpret_cast<float4*>(ov)[q];
    }
}

// ---------------- launch ----------------
extern "C" void kernel_launch(void* const* d_in, const int* in_sizes, int n_in,
                              void* d_out, int out_size) {
    const float* node_s = (const float*)d_in[0];
    const float* node_v = (const float*)d_in[1];
    const float* edge_s = (const float*)d_in[3];
    const float* edge_v = (const float*)d_in[4];
    const int*   eidx   = (const int*)d_in[5];
    const float* W1ss = (const float*)d_in[6];
    const float* W1sv = (const float*)d_in[7];
    const float* W1vs = (const float*)d_in[8];
    const float* W1vvs = (const float*)d_in[9];
    const float* W1vvv = (const float*)d_in[10];
    const float* W2ss = (const float*)d_in[11];
    const float* W2sv = (const float*)d_in[12];
    const float* W2vs = (const float*)d_in[13];
    const float* W2vvs = (const float*)d_in[14];
    const float* W2vvv = (const float*)d_in[15];
    const float* Lms = (const float*)d_in[16];
    const float* Lmv = (const float*)d_in[17];
    const float* W3ss = (const float*)d_in[18];
    const float* W3sv = (const float*)d_in[19];
    const float* W3vs = (const float*)d_in[20];
    const float* W3vvs = (const float*)d_in[21];
    const float* W3vvv = (const float*)d_in[22];
    const float* Lus = (const float*)d_in[23];
    const float* Luv = (const float*)d_in[24];
    float* out = (float*)d_out;

    int N = in_sizes[0] / 16;
    int E = in_sizes[3] / 8;
    int gE = (E + 127) / 128;
    int gN = (N + 127) / 128;

    zero_kernel<<<(N * 80 + 255) / 256, 256>>>(N * 80);
    stage1_kernel<<<gE, 128>>>(node_s, node_v, eidx, W1ss, W1sv, W1vs, W1vvs, W1vvv, E);
    stage2_kernel<<<gE, 128>>>(edge_s, edge_v, eidx, W2ss, W2vvs, W2sv, W2vs, W2vvv, E);
    fold_kernel<<<(N + 255) / 256, 256>>>(Lms, Lmv, N);
    update_kernel<<<gN, 128>>>(node_s, node_v, W3ss, W3vvs, W3sv, W3vs, W3vvv, Lus, Luv, out, N);
}